// round 16
// baseline (speedup 1.0000x reference)
#include <cuda_runtime.h>
#include <cuda_fp16.h>
#include <cstdint>

// ---------------------------------------------------------------------------
// MMD loss via mma.sync fp16 gram (fp32 accum) + fused fp32 gaussian epilogue
//   loss = (1/ns^2) * sum_{i,j} s_i s_j K_ij
//   K_ij = u + u^2 + u^4 + u^8 + u^16,  u = 2^(-l2_ij*c4), c4 = log2e/(bw*16)
//   l2_ij = sq_i + sq_j - 2 g_ij ; bandwidth via O(nD) identity.
// R15 (resubmit; prior round was an infra failure): 128x64 tiles -> 32
// accumulators/thread -> 3 CTAs/SM (6 warps/SMSP) so one CTA's tensor
// mainloop overlaps another's FMA epilogue (R14 analysis: the two phases are
// equal-sized and were serializing at 2 CTAs/SM).
// Tile cover: (ti, tj), tj in [2ti, 127]; tj∈{2ti,2ti+1} = diagonal halves
// (weight 1), tj>=2ti+2 strictly upper (weight 2). 4160 CTAs.
// 3 launches: prep -> permute(+c4) -> mmd(+writeout,+state reset).
// ---------------------------------------------------------------------------

#define NS     4096
#define DDIM   256
#define NTOT   8192
#define BM     128
#define BN     64
#define BKC    64
#define NCHUNK (DDIM / BKC)     // 4
#define NTILES 64               // 128-row tiles
#define NJT    128              // 64-col tiles
#define NBLK   4160             // sum_{ti} (128 - 2 ti)

#define ASTG   16384            // A stage: 8 rowblocks x 4 ksteps x 512B
#define BSTG   8192             // B stage: 8 colblocks x 4 ksteps x 256B

// smem byte offsets (3 stages each)
#define SM_A0   0
#define SM_B0   (3 * ASTG)              // 49152
#define SM_SQI  (3 * ASTG + 3 * BSTG)   // 73728
#define SM_SQJ  (SM_SQI + 512)
#define SM_RED  (SM_SQI + 1024)
#define SMEM_BYTES (SM_RED + 1024)      // 75776 -> 3 CTAs/SM

__device__ __half   g_convA[NTOT * DDIM];  // A-fragment order, 4 MB
__device__ __half   g_convB[NTOT * DDIM];  // B-fragment order, 4 MB
__device__ float    g_sq[NTOT];
__device__ float    g_colsum[DDIM];        // zero-init; reset by mmd tail
__device__ double   g_ssum;                // zero-init; reset by mmd tail
__device__ double   g_acc;                 // zero-init; reset by mmd tail
__device__ float    g_c4;
__device__ unsigned g_done;                // zero-init; reset by mmd tail

// ---------------------------------------------------------------------------
__device__ __forceinline__ float ex2f(float x) {
    float r; asm("ex2.approx.ftz.f32 %0, %1;" : "=f"(r) : "f"(x)); return r;
}
__device__ __forceinline__ uint32_t smem_u32(const void* p) {
    uint32_t a;
    asm("{ .reg .u64 t; cvta.to.shared.u64 t, %1; cvt.u32.u64 %0, t; }"
        : "=r"(a) : "l"(p));
    return a;
}
__device__ __forceinline__ void cp16(uint32_t dst, const void* src) {
    asm volatile("cp.async.cg.shared.global [%0], [%1], 16;"
                 :: "r"(dst), "l"(src));
}
__device__ __forceinline__ void cp_commit() {
    asm volatile("cp.async.commit_group;" ::: "memory");
}
template <int N>
__device__ __forceinline__ void cp_wait() {
    asm volatile("cp.async.wait_group %0;" :: "n"(N) : "memory");
}
__device__ __forceinline__ void mma_f16(float c[4], const uint4 a,
                                        const uint2 b) {
    asm volatile(
        "mma.sync.aligned.m16n8k16.row.col.f32.f16.f16.f32 "
        "{%0,%1,%2,%3},{%4,%5,%6,%7},{%8,%9},{%0,%1,%2,%3};"
        : "+f"(c[0]), "+f"(c[1]), "+f"(c[2]), "+f"(c[3])
        : "r"(a.x), "r"(a.y), "r"(a.z), "r"(a.w), "r"(b.x), "r"(b.y));
}
__device__ __forceinline__ const float* srow(const float* __restrict__ src,
                                             const float* __restrict__ tgt,
                                             int row) {
    return (row < NS) ? (src + (size_t)row * DDIM)
                      : (tgt + (size_t)(row - NS) * DDIM);
}
__device__ __forceinline__ uint32_t pack_h2(float lo, float hi) {
    __half2 h = __floats2half2_rn(lo, hi);
    return *(uint32_t*)&h;
}

// ---------------------------------------------------------------------------
// prep: sumsq per row + colsums + total sumsq (R8 verbatim).
__global__ void prep_kernel(const float* __restrict__ src,
                            const float* __restrict__ tgt) {
    const int tid  = threadIdx.x;
    const int w    = tid >> 5;
    const int lane = tid & 31;
    const int b    = blockIdx.x;
    const float* base = (b < 128) ? (src + (size_t)b * 32 * DDIM)
                                  : (tgt + (size_t)(b - 128) * 32 * DDIM);
    __shared__ float wsum[8];

    float mysq = 0.0f;
    #pragma unroll
    for (int it = 0; it < 4; it++) {
        int r = it * 8 + w;
        const float* p = base + (size_t)r * DDIM;
        float4 a = *(const float4*)(p + lane * 8);
        float4 c = *(const float4*)(p + lane * 8 + 4);
        float s = a.x*a.x + a.y*a.y + a.z*a.z + a.w*a.w
                + c.x*c.x + c.y*c.y + c.z*c.z + c.w*c.w;
        #pragma unroll
        for (int o = 16; o > 0; o >>= 1) s += __shfl_xor_sync(0xFFFFFFFFu, s, o);
        if (lane == 0) { g_sq[b * 32 + r] = s; mysq += s; }
    }
    if (lane == 0) wsum[w] = mysq;

    float cs = 0.0f;
    #pragma unroll 8
    for (int r = 0; r < 32; r++) cs += base[(size_t)r * DDIM + tid];
    atomicAdd(&g_colsum[tid], cs);

    __syncthreads();
    if (tid == 0) {
        float tot = 0.0f;
        #pragma unroll
        for (int i = 0; i < 8; i++) tot += wsum[i];
        atomicAdd(&g_ssum, (double)tot);
    }
}

// permute: c4 finalize (block 0 publishes g_c4) + fp16 fragment copies.
__global__ void permute_kernel(const float* __restrict__ src,
                               const float* __restrict__ tgt) {
    __shared__ double wred[8];
    const int tid  = threadIdx.x;
    const int w    = tid >> 5;
    const int lane = tid & 31;

    if (blockIdx.x == 0) {
        float c = g_colsum[tid];
        double v = (double)c * (double)c;
        #pragma unroll
        for (int o = 16; o > 0; o >>= 1)
            v += __shfl_xor_sync(0xFFFFFFFFu, v, o);
        if (lane == 0) wred[w] = v;
        __syncthreads();
        if (tid == 0) {
            double V = 0.0;
            #pragma unroll
            for (int i = 0; i < 8; i++) V += wred[i];
            double S      = g_ssum;
            double n      = (double)NTOT;
            double sum_l2 = 2.0 * n * S - 2.0 * V;
            double bw     = sum_l2 / (n * n - n);
            bw /= 4.0;                               // KERNEL_MUL^(NUM//2)
            g_c4 = (float)(1.4426950408889634 / (bw * 16.0));
        }
    }

    if (blockIdx.x < 1024) {
        int o    = blockIdx.x * 256 + tid;          // 16B unit index
        int RB   = o >> 9;
        int rem  = o & 511;
        int KS   = rem >> 5;
        int ln   = rem & 31;
        int g    = ln >> 2;
        int t4   = ln & 3;
        int r    = RB * 16 + g;
        int k    = KS * 16 + t4 * 2;
        const float* p0 = srow(src, tgt, r);
        const float* p1 = srow(src, tgt, r + 8);
        uint4 v;
        v.x = pack_h2(p0[k],     p0[k + 1]);
        v.y = pack_h2(p1[k],     p1[k + 1]);
        v.z = pack_h2(p0[k + 8], p0[k + 9]);
        v.w = pack_h2(p1[k + 8], p1[k + 9]);
        *(uint4*)((char*)g_convA + (size_t)o * 16) = v;
    } else {
        int o    = (blockIdx.x - 1024) * 256 + tid; // 8B unit index
        int CB   = o >> 9;
        int rem  = o & 511;
        int KS   = rem >> 5;
        int ln   = rem & 31;
        int g    = ln >> 2;
        int t4   = ln & 3;
        int c    = CB * 8 + g;
        int k    = KS * 16 + t4 * 2;
        const float* p = srow(src, tgt, c);
        uint2 v;
        v.x = pack_h2(p[k],     p[k + 1]);
        v.y = pack_h2(p[k + 8], p[k + 9]);
        *(uint2*)((char*)g_convB + (size_t)o * 8) = v;
    }
}

// ---------------------------------------------------------------------------
// 128x64 tile kernel: 8 warps as 4(m) x 2(n), warp tile 32x32, 32 acc/thread,
// 3 CTAs/SM. Last block writes out and resets state for graph replay.
__global__ void __launch_bounds__(256, 3)
mmd_kernel(float* __restrict__ out) {
    // decode idx -> (ti, tj): C(ti) = ti*(129-ti), tj = 2ti + (idx - C(ti))
    int idx = blockIdx.x;
    int ti = (int)((129.0 - sqrt(129.0 * 129.0 - 4.0 * (double)idx)) * 0.5);
    if (ti > NTILES - 1) ti = NTILES - 1;
    while (ti > 0 && idx < ti * (129 - ti)) ti--;
    while (idx >= (ti + 1) * (128 - ti)) ti++;
    const int tj = 2 * ti + (idx - ti * (129 - ti));

    extern __shared__ char smem[];
    const uint32_t sbase = smem_u32(smem);
    float* sqi = (float*)(smem + SM_SQI);
    float* sqj = (float*)(smem + SM_SQJ);
    float* red = (float*)(smem + SM_RED);

    const int tid  = threadIdx.x;
    const int wid  = tid >> 5;
    const int lane = tid & 31;
    const int g    = lane >> 2;
    const int t4   = lane & 3;
    const int wm   = wid & 3;      // 4 warps over 128 rows
    const int wn   = wid >> 2;     // 2 warps over 64 cols

    const int i0 = ti * BM;
    const int j0 = tj * BN;
    const int Rb = ti * 8;         // A 16-row block base
    const int Cb = tj * 8;         // B 8-col block base

    if (tid < 128)      sqi[tid]       = g_sq[i0 + tid];
    else if (tid < 192) sqj[tid - 128] = g_sq[j0 + tid - 128];

    // cp.async: per chunk, A = 1024 16B units (4/thread), B = 512 (2/thread)
    #pragma unroll
    for (int c = 0; c < 2; c++) {
        #pragma unroll
        for (int l = 0; l < 4; l++) {
            int ia = tid + l * 256;
            cp16(sbase + SM_A0 + c * ASTG + ia * 16,
                 (const char*)g_convA + (size_t)(Rb + (ia >> 7)) * 8192
                     + (c * 4 + ((ia >> 5) & 3)) * 512 + (ia & 31) * 16);
        }
        #pragma unroll
        for (int l = 0; l < 2; l++) {
            int ia = tid + l * 256;
            cp16(sbase + SM_B0 + c * BSTG + ia * 16,
                 (const char*)g_convB + (size_t)(Cb + (ia >> 6)) * 4096
                     + (c * 4 + ((ia >> 4) & 3)) * 256 + (ia & 15) * 16);
        }
        cp_commit();
    }

    float acc[2][4][4];
    #pragma unroll
    for (int a = 0; a < 2; a++)
        #pragma unroll
        for (int b = 0; b < 4; b++)
            #pragma unroll
            for (int f = 0; f < 4; f++) acc[a][b][f] = 0.0f;

    int st_c = 0, st_p = 2;
    #pragma unroll 1
    for (int c = 0; c < NCHUNK; c++) {
        if (c + 2 < NCHUNK) {
            const int cc = c + 2;
            #pragma unroll
            for (int l = 0; l < 4; l++) {
                int ia = tid + l * 256;
                cp16(sbase + SM_A0 + st_p * ASTG + ia * 16,
                     (const char*)g_convA + (size_t)(Rb + (ia >> 7)) * 8192
                         + (cc * 4 + ((ia >> 5) & 3)) * 512 + (ia & 31) * 16);
            }
            #pragma unroll
            for (int l = 0; l < 2; l++) {
                int ia = tid + l * 256;
                cp16(sbase + SM_B0 + st_p * BSTG + ia * 16,
                     (const char*)g_convB + (size_t)(Cb + (ia >> 6)) * 4096
                         + (cc * 4 + ((ia >> 4) & 3)) * 256 + (ia & 15) * 16);
            }
            cp_commit();
            cp_wait<2>();
        } else if (c + 1 < NCHUNK) {
            cp_wait<1>();
        } else {
            cp_wait<0>();
        }
        __syncthreads();

        const char* As = smem + SM_A0 + st_c * ASTG;
        const char* Bs = smem + SM_B0 + st_c * BSTG;

        #pragma unroll
        for (int s = 0; s < 4; s++) {
            uint4 af[2];
            uint2 bf[4];
            #pragma unroll
            for (int ma = 0; ma < 2; ma++)
                af[ma] = *(const uint4*)(As + (wm * 2 + ma) * 2048 + s * 512
                                            + lane * 16);
            #pragma unroll
            for (int nb = 0; nb < 4; nb++)
                bf[nb] = *(const uint2*)(Bs + (wn * 4 + nb) * 1024 + s * 256
                                            + lane * 8);
            #pragma unroll
            for (int ma = 0; ma < 2; ma++)
                #pragma unroll
                for (int nb = 0; nb < 4; nb++)
                    mma_f16(acc[ma][nb], af[ma], bf[nb]);
        }
        __syncthreads();

        st_c = (st_c == 2) ? 0 : st_c + 1;
        st_p = (st_p == 2) ? 0 : st_p + 1;
    }

    // --- epilogue ---
    const float c4 = g_c4;
    float si[2][2], sj[4][2];
    #pragma unroll
    for (int ma = 0; ma < 2; ma++) {
        si[ma][0] = sqi[wm * 32 + ma * 16 + g];
        si[ma][1] = sqi[wm * 32 + ma * 16 + g + 8];
    }
    #pragma unroll
    for (int nb = 0; nb < 4; nb++) {
        sj[nb][0] = sqj[wn * 32 + nb * 8 + 2 * t4];
        sj[nb][1] = sqj[wn * 32 + nb * 8 + 2 * t4 + 1];
    }

    float part = 0.0f;
    #pragma unroll
    for (int ma = 0; ma < 2; ma++) {
        #pragma unroll
        for (int nb = 0; nb < 4; nb++) {
            #pragma unroll
            for (int f = 0; f < 4; f++) {
                float nl2 = 2.0f * acc[ma][nb][f] - si[ma][f >> 1] - sj[nb][f & 1];
                float u   = ex2f(nl2 * c4);
                float u2  = u  * u;
                float u4  = u2 * u2;
                float u8  = u4 * u4;
                float u16 = u8 * u8;
                part += (u + u2) + (u4 + u8) + u16;
            }
        }
    }

    // weight: diagonal halves (tj = 2ti or 2ti+1) once, strictly-upper twice
    float w  = (tj >= 2 * ti + 2) ? 2.0f : 1.0f;
    float sg = ((ti < NTILES / 2) == (tj < NJT / 2)) ? 1.0f : -1.0f;
    part *= w * sg;

    red[tid] = part;
    __syncthreads();
    #pragma unroll
    for (int s = 128; s > 0; s >>= 1) {
        if (tid < s) red[tid] += red[tid + s];
        __syncthreads();
    }
    if (tid == 0) {
        atomicAdd(&g_acc, (double)red[0]);
        __threadfence();
        unsigned old = atomicAdd(&g_done, 1u);
        if (old == NBLK - 1) {
            double v = atomicAdd(&g_acc, 0.0);   // atomic read after fence
            out[0] = (float)(v / ((double)NS * (double)NS));
            #pragma unroll 8
            for (int i = 0; i < DDIM; i++) g_colsum[i] = 0.0f;
            g_ssum = 0.0;
            g_acc  = 0.0;
            __threadfence();
            g_done = 0u;
        }
    }
}

// ---------------------------------------------------------------------------
extern "C" void kernel_launch(void* const* d_in, const int* in_sizes, int n_in,
                              void* d_out, int out_size) {
    const float* src = (const float*)d_in[0];
    const float* tgt = (const float*)d_in[1];
    float* out = (float*)d_out;

    cudaFuncSetAttribute(mmd_kernel,
                         cudaFuncAttributeMaxDynamicSharedMemorySize, SMEM_BYTES);

    prep_kernel<<<256, 256>>>(src, tgt);
    permute_kernel<<<3072, 256>>>(src, tgt);
    mmd_kernel<<<NBLK, 256, SMEM_BYTES>>>(out);
}

// round 17
// speedup vs baseline: 1.1409x; 1.1409x over previous
#include <cuda_runtime.h>
#include <cuda_fp16.h>
#include <cstdint>

// ---------------------------------------------------------------------------
// MMD loss via mma.sync fp16 gram (fp32 accum) + fused fp32 gaussian epilogue
//   loss = (1/ns^2) * sum_{i,j} s_i s_j K_ij
//   K_ij = u + u^2 + u^4 + u^8 + u^16,  u = 2^(-l2_ij*c4), c4 = log2e/(bw*16)
//   l2_ij = sq_i + sq_j - 2 g_ij ; bandwidth via O(nD) identity.
// R17: BARRIER-FREE mainloop. R12 profile showed nothing saturated
// (tensor 46%, fma 16%, L2 14%, issue 36%) -> latency/sync-bound. Fragment-
// ordered g_convA/g_convB make every lane's MMA operand a contiguous,
// warp-coalesced 16B/8B global load, so operands come straight from L1/L2:
// no smem staging, no cp.async, no mainloop __syncthreads. Warps run fully
// independent; only the final 8-value block reduce synchronizes.
// 128x128 tiles, triangular grid (2080 CTAs), off-diagonal weight 2.
// 3 launches: prep -> permute(+c4) -> mmd(+writeout,+state reset).
// ---------------------------------------------------------------------------

#define NS     4096
#define DDIM   256
#define NTOT   8192
#define BM     128
#define NTILES (NTOT / BM)      // 64
#define NBLK   (NTILES * (NTILES + 1) / 2)   // 2080

__device__ __half   g_convA[NTOT * DDIM];  // A-fragment order, 4 MB
__device__ __half   g_convB[NTOT * DDIM];  // B-fragment order, 4 MB
__device__ float    g_sq[NTOT];
__device__ float    g_colsum[DDIM];        // zero-init; reset by mmd tail
__device__ double   g_ssum;                // zero-init; reset by mmd tail
__device__ double   g_acc;                 // zero-init; reset by mmd tail
__device__ float    g_c4;
__device__ unsigned g_done;                // zero-init; reset by mmd tail

// ---------------------------------------------------------------------------
__device__ __forceinline__ float ex2f(float x) {
    float r; asm("ex2.approx.ftz.f32 %0, %1;" : "=f"(r) : "f"(x)); return r;
}
__device__ __forceinline__ void mma_f16(float c[4], const uint4 a,
                                        const uint2 b) {
    asm volatile(
        "mma.sync.aligned.m16n8k16.row.col.f32.f16.f16.f32 "
        "{%0,%1,%2,%3},{%4,%5,%6,%7},{%8,%9},{%0,%1,%2,%3};"
        : "+f"(c[0]), "+f"(c[1]), "+f"(c[2]), "+f"(c[3])
        : "r"(a.x), "r"(a.y), "r"(a.z), "r"(a.w), "r"(b.x), "r"(b.y));
}
__device__ __forceinline__ const float* srow(const float* __restrict__ src,
                                             const float* __restrict__ tgt,
                                             int row) {
    return (row < NS) ? (src + (size_t)row * DDIM)
                      : (tgt + (size_t)(row - NS) * DDIM);
}
__device__ __forceinline__ uint32_t pack_h2(float lo, float hi) {
    __half2 h = __floats2half2_rn(lo, hi);
    return *(uint32_t*)&h;
}

// ---------------------------------------------------------------------------
// prep: sumsq per row + colsums + total sumsq (R8 verbatim).
__global__ void prep_kernel(const float* __restrict__ src,
                            const float* __restrict__ tgt) {
    const int tid  = threadIdx.x;
    const int w    = tid >> 5;
    const int lane = tid & 31;
    const int b    = blockIdx.x;
    const float* base = (b < 128) ? (src + (size_t)b * 32 * DDIM)
                                  : (tgt + (size_t)(b - 128) * 32 * DDIM);
    __shared__ float wsum[8];

    float mysq = 0.0f;
    #pragma unroll
    for (int it = 0; it < 4; it++) {
        int r = it * 8 + w;
        const float* p = base + (size_t)r * DDIM;
        float4 a = *(const float4*)(p + lane * 8);
        float4 c = *(const float4*)(p + lane * 8 + 4);
        float s = a.x*a.x + a.y*a.y + a.z*a.z + a.w*a.w
                + c.x*c.x + c.y*c.y + c.z*c.z + c.w*c.w;
        #pragma unroll
        for (int o = 16; o > 0; o >>= 1) s += __shfl_xor_sync(0xFFFFFFFFu, s, o);
        if (lane == 0) { g_sq[b * 32 + r] = s; mysq += s; }
    }
    if (lane == 0) wsum[w] = mysq;

    float cs = 0.0f;
    #pragma unroll 8
    for (int r = 0; r < 32; r++) cs += base[(size_t)r * DDIM + tid];
    atomicAdd(&g_colsum[tid], cs);

    __syncthreads();
    if (tid == 0) {
        float tot = 0.0f;
        #pragma unroll
        for (int i = 0; i < 8; i++) tot += wsum[i];
        atomicAdd(&g_ssum, (double)tot);
    }
}

// permute: c4 finalize (block 0 publishes g_c4) + fp16 fragment copies.
__global__ void permute_kernel(const float* __restrict__ src,
                               const float* __restrict__ tgt) {
    __shared__ double wred[8];
    const int tid  = threadIdx.x;
    const int w    = tid >> 5;
    const int lane = tid & 31;

    if (blockIdx.x == 0) {
        float c = g_colsum[tid];
        double v = (double)c * (double)c;
        #pragma unroll
        for (int o = 16; o > 0; o >>= 1)
            v += __shfl_xor_sync(0xFFFFFFFFu, v, o);
        if (lane == 0) wred[w] = v;
        __syncthreads();
        if (tid == 0) {
            double V = 0.0;
            #pragma unroll
            for (int i = 0; i < 8; i++) V += wred[i];
            double S      = g_ssum;
            double n      = (double)NTOT;
            double sum_l2 = 2.0 * n * S - 2.0 * V;
            double bw     = sum_l2 / (n * n - n);
            bw /= 4.0;                               // KERNEL_MUL^(NUM//2)
            g_c4 = (float)(1.4426950408889634 / (bw * 16.0));
        }
    }

    if (blockIdx.x < 1024) {
        int o    = blockIdx.x * 256 + tid;          // 16B unit index
        int RB   = o >> 9;
        int rem  = o & 511;
        int KS   = rem >> 5;
        int ln   = rem & 31;
        int g    = ln >> 2;
        int t4   = ln & 3;
        int r    = RB * 16 + g;
        int k    = KS * 16 + t4 * 2;
        const float* p0 = srow(src, tgt, r);
        const float* p1 = srow(src, tgt, r + 8);
        uint4 v;
        v.x = pack_h2(p0[k],     p0[k + 1]);
        v.y = pack_h2(p1[k],     p1[k + 1]);
        v.z = pack_h2(p0[k + 8], p0[k + 9]);
        v.w = pack_h2(p1[k + 8], p1[k + 9]);
        *(uint4*)((char*)g_convA + (size_t)o * 16) = v;
    } else {
        int o    = (blockIdx.x - 1024) * 256 + tid; // 8B unit index
        int CB   = o >> 9;
        int rem  = o & 511;
        int KS   = rem >> 5;
        int ln   = rem & 31;
        int g    = ln >> 2;
        int t4   = ln & 3;
        int c    = CB * 8 + g;
        int k    = KS * 16 + t4 * 2;
        const float* p = srow(src, tgt, c);
        uint2 v;
        v.x = pack_h2(p[k],     p[k + 1]);
        v.y = pack_h2(p[k + 8], p[k + 9]);
        *(uint2*)((char*)g_convB + (size_t)o * 8) = v;
    }
}

// ---------------------------------------------------------------------------
// Barrier-free 128x128 tile kernel: MMA operands via direct coalesced LDG
// from fragment-ordered buffers; no smem staging; warps fully independent.
// 8 warps as 2(m) x 4(n), warp tile 64x32, 64 acc/thread, 2 CTAs/SM.
__global__ void __launch_bounds__(256, 2)
mmd_kernel(float* __restrict__ out) {
    // triangular decode: idx -> (ti, tj), ti <= tj
    int idx = blockIdx.x;
    int ti = (int)((129.0 - sqrt(129.0 * 129.0 - 8.0 * (double)idx)) * 0.5);
    if (ti > NTILES - 1) ti = NTILES - 1;
    while (ti > 0 && idx < ti * NTILES - ti * (ti - 1) / 2) ti--;
    while (idx >= (ti + 1) * NTILES - (ti + 1) * ti / 2) ti++;
    const int tj = ti + (idx - (ti * NTILES - ti * (ti - 1) / 2));

    const int tid  = threadIdx.x;
    const int wid  = tid >> 5;
    const int lane = tid & 31;
    const int g    = lane >> 2;
    const int t4   = lane & 3;
    const int wm   = wid & 1;      // 2 warps over 128 rows (64 each)
    const int wn   = wid >> 1;     // 4 warps over 128 cols (32 each)

    const int i0 = ti * BM;
    const int j0 = tj * BM;

    // per-warp operand base pointers (fragment-ordered, lane-coalesced)
    // A unit: (RB, KS, lane) at byte ((RB*16+KS)*32 + lane)*16, RB = ti*8 + wm*4 + ma
    // B unit: (CB, KS, lane) at byte ((CB*16+KS)*32 + lane)*8,  CB = tj*16 + wn*4 + nb
    const char* Abase = (const char*)g_convA
        + ((size_t)(ti * 8 + wm * 4) * 16) * 512 + (size_t)lane * 16;
    const char* Bbase = (const char*)g_convB
        + ((size_t)(tj * 16 + wn * 4) * 16) * 256 + (size_t)lane * 8;

    float acc[4][4][4];
    #pragma unroll
    for (int a = 0; a < 4; a++)
        #pragma unroll
        for (int b = 0; b < 4; b++)
            #pragma unroll
            for (int f = 0; f < 4; f++) acc[a][b][f] = 0.0f;

    // barrier-free mainloop: 16 k-steps fully unrolled, 8 LDG + 16 HMMA each
    #pragma unroll
    for (int ks = 0; ks < 16; ks++) {
        uint4 af[4];
        uint2 bf[4];
        #pragma unroll
        for (int ma = 0; ma < 4; ma++)
            af[ma] = __ldg((const uint4*)(Abase + ((size_t)ma * 16 + ks) * 512));
        #pragma unroll
        for (int nb = 0; nb < 4; nb++)
            bf[nb] = __ldg((const uint2*)(Bbase + ((size_t)nb * 16 + ks) * 256));
        #pragma unroll
        for (int ma = 0; ma < 4; ma++)
            #pragma unroll
            for (int nb = 0; nb < 4; nb++)
                mma_f16(acc[ma][nb], af[ma], bf[nb]);
    }

    // --- epilogue (R8 math verbatim; sq via direct LDG) ---
    const float c4 = g_c4;
    float si[4][2], sj[4][2];
    #pragma unroll
    for (int ma = 0; ma < 4; ma++) {
        si[ma][0] = __ldg(&g_sq[i0 + wm * 64 + ma * 16 + g]);
        si[ma][1] = __ldg(&g_sq[i0 + wm * 64 + ma * 16 + g + 8]);
    }
    #pragma unroll
    for (int nb = 0; nb < 4; nb++) {
        sj[nb][0] = __ldg(&g_sq[j0 + wn * 32 + nb * 8 + 2 * t4]);
        sj[nb][1] = __ldg(&g_sq[j0 + wn * 32 + nb * 8 + 2 * t4 + 1]);
    }

    float part = 0.0f;
    #pragma unroll
    for (int ma = 0; ma < 4; ma++) {
        #pragma unroll
        for (int nb = 0; nb < 4; nb++) {
            #pragma unroll
            for (int f = 0; f < 4; f++) {
                float nl2 = 2.0f * acc[ma][nb][f] - si[ma][f >> 1] - sj[nb][f & 1];
                float u   = ex2f(nl2 * c4);
                float u2  = u  * u;
                float u4  = u2 * u2;
                float u8  = u4 * u4;
                float u16 = u8 * u8;
                part += (u + u2) + (u4 + u8) + u16;
            }
        }
    }

    float w  = (ti == tj) ? 1.0f : 2.0f;
    float sg = ((ti < NTILES / 2) == (tj < NTILES / 2)) ? 1.0f : -1.0f;
    part *= w * sg;

    // reduce: intra-warp shuffle, 8 partials via smem, warp 0 finishes
    #pragma unroll
    for (int o = 16; o > 0; o >>= 1)
        part += __shfl_xor_sync(0xFFFFFFFFu, part, o);

    __shared__ float red[8];
    if (lane == 0) red[wid] = part;
    __syncthreads();
    if (tid == 0) {
        float tot = 0.0f;
        #pragma unroll
        for (int i = 0; i < 8; i++) tot += red[i];
        atomicAdd(&g_acc, (double)tot);
        __threadfence();
        unsigned old = atomicAdd(&g_done, 1u);
        if (old == NBLK - 1) {
            double v = atomicAdd(&g_acc, 0.0);   // atomic read after fence
            out[0] = (float)(v / ((double)NS * (double)NS));
            #pragma unroll 8
            for (int i = 0; i < DDIM; i++) g_colsum[i] = 0.0f;
            g_ssum = 0.0;
            g_acc  = 0.0;
            __threadfence();
            g_done = 0u;
        }
    }
}

// ---------------------------------------------------------------------------
extern "C" void kernel_launch(void* const* d_in, const int* in_sizes, int n_in,
                              void* d_out, int out_size) {
    const float* src = (const float*)d_in[0];
    const float* tgt = (const float*)d_in[1];
    float* out = (float*)d_out;

    prep_kernel<<<256, 256>>>(src, tgt);
    permute_kernel<<<3072, 256>>>(src, tgt);
    mmd_kernel<<<NBLK, 256>>>(out);
}